// round 3
// baseline (speedup 1.0000x reference)
#include <cuda_runtime.h>

#define NN 100000
#define DD 64
#define DV4 16   // 64 floats = 16 float4 per row

__device__ int   g_outdeg[NN];
__device__ int   g_indeg[NN];
__device__ float g_norml[NN];
__device__ float g_normr[NN];

__global__ void k_zero_deg() {
    int i = blockIdx.x * blockDim.x + threadIdx.x;
    if (i < NN) { g_outdeg[i] = 0; g_indeg[i] = 0; }
}

__global__ void k_count(const int* __restrict__ src,
                        const int* __restrict__ dst, int e) {
    int i = blockIdx.x * blockDim.x + threadIdx.x;
    if (i < e) {
        atomicAdd(&g_outdeg[src[i]], 1);
        atomicAdd(&g_indeg[dst[i]], 1);
    }
}

__global__ void k_norm() {
    int i = blockIdx.x * blockDim.x + threadIdx.x;
    if (i < NN) {
        g_norml[i] = rsqrtf(fmaxf((float)g_outdeg[i], 1.0f) + 1.0f);
        g_normr[i] = rsqrtf(fmaxf((float)g_indeg[i], 1.0f) + 1.0f);
    }
}

// 16 threads per edge; each thread moves one float4 of the 64-float row.
__global__ void k_scatter(const float4* __restrict__ feat,
                          const int* __restrict__ src,
                          const int* __restrict__ dst,
                          float* __restrict__ out, int e) {
    int t = blockIdx.x * blockDim.x + threadIdx.x;
    int edge = t >> 4;
    int lane = t & 15;
    if (edge >= e) return;
    int s = __ldg(&src[edge]);   // per-lane redundant, but a single warp instr (SIMT)
    int d = __ldg(&dst[edge]);
    float nl = g_norml[s];
    float4 v = __ldg(&feat[s * DV4 + lane]);
    v.x *= nl; v.y *= nl; v.z *= nl; v.w *= nl;
    float* addr = out + (size_t)d * DD + lane * 4;
    // Vector fire-and-forget reduction (sm_90+): 1 RED.128 per lane, no return.
    asm volatile("red.global.add.v4.f32 [%0], {%1, %2, %3, %4};"
                 :: "l"(addr), "f"(v.x), "f"(v.y), "f"(v.z), "f"(v.w)
                 : "memory");
}

__global__ void k_final(const float4* __restrict__ feat,
                        float4* __restrict__ out) {
    int i = blockIdx.x * blockDim.x + threadIdx.x;
    if (i < NN * DV4) {
        float nr = g_normr[i >> 4];
        float4 f = __ldg(&feat[i]);
        float4 h = out[i];
        out[i] = make_float4((f.x + h.x) * nr, (f.y + h.y) * nr,
                             (f.z + h.z) * nr, (f.w + h.w) * nr);
    }
}

extern "C" void kernel_launch(void* const* d_in, const int* in_sizes, int n_in,
                              void* d_out, int out_size) {
    const float4* feat = (const float4*)d_in[0];
    const int*    src  = (const int*)d_in[1];
    const int*    dst  = (const int*)d_in[2];
    int e = in_sizes[1];
    float* out = (float*)d_out;

    // d_out is poisoned 0xAA — zero it (accumulator for h_neigh).
    cudaMemsetAsync(d_out, 0, (size_t)NN * DD * sizeof(float));
    k_zero_deg<<<(NN + 255) / 256, 256>>>();
    k_count<<<(e + 255) / 256, 256>>>(src, dst, e);
    k_norm<<<(NN + 255) / 256, 256>>>();

    long long tot = (long long)e * DV4;
    k_scatter<<<(int)((tot + 255) / 256), 256>>>(feat, src, dst, out, e);
    k_final<<<(NN * DV4 + 255) / 256, 256>>>(feat, (float4*)d_out);
}